// round 1
// baseline (speedup 1.0000x reference)
#include <cuda_runtime.h>
#include <cuda_fp16.h>
#include <math.h>
#include <stdint.h>

// ---------------- problem constants ----------------
#define ZDIM   17728      // 3*56*56 + 64*128 + 128
#define HID    4096
#define NBATCH 128
#define N2PAD  17792      // 139 * 128
#define NSTEPS 11
#define KB1    277        // 17728 / 64 k-blocks for GEMM1
#define KB2    64         // 4096  / 64 k-blocks for GEMM2
#define SPLITK 4
#define KCHUNK 70         // ceil(277/4)

// ---------------- device scratch (no allocs allowed) ----------------
__device__ __half g_W1h[(size_t)ZDIM * HID];       // 145.2 MB  fp16 W1 (first 17728 rows)
__device__ __half g_W2h[(size_t)HID * N2PAD];      // 145.8 MB  fp16 W2, N padded with zeros
__device__ __half g_zh [(size_t)NBATCH * ZDIM];    // 4.5 MB    fp16 activations z
__device__ __half g_h  [(size_t)NBATCH * HID];     // 1 MB      fp16 hidden h
__device__ float  g_hpart[(size_t)SPLITK * NBATCH * HID];  // 8 MB split-K partials
__device__ float  g_emb[12 * NBATCH * 6];          // time embeddings

// ---------------- time grid + embedding ----------------
__global__ void emb_kernel(const float* __restrict__ cur, const float* __restrict__ tar) {
    int b = threadIdx.x;
    if (b >= NBATCH) return;
    const float P[3] = {24.0f, 7.0f, 365.0f};
    float tc[3];
    for (int j = 0; j < 3; j++) tc[j] = cur[b * 3 + j];
    int r = 0;
    for (int j = 0; j < 3; j++) {
        float s = cur[b * 3 + j], e = tar[b * 3 + j];
        bool wrap = s > e;
        float ea = wrap ? e + P[j] : e;
        for (int k = 0; k < 4; k++) {
            float frac = (float)k / 3.0f;
            float inter = s + (ea - s) * frac;
            if (wrap) inter = fmodf(inter, P[j]);
            tc[j] = inter;
            for (int jj = 0; jj < 3; jj++) {
                float ph = 6.2831853071795864769f * tc[jj] / P[jj];
                g_emb[(r * NBATCH + b) * 6 + jj]     = sinf(ph);
                g_emb[(r * NBATCH + b) * 6 + 3 + jj] = cosf(ph);
            }
            r++;
        }
    }
}

// ---------------- z0 build (writes fp32 z into d_out and fp16 copy) ----------------
__global__ void z0_kernel(const float* __restrict__ freq, const int* __restrict__ seq,
                          const int* __restrict__ uid, const float* __restrict__ fuse,
                          const int* __restrict__ n_poi, float* __restrict__ zout) {
    int idx = blockIdx.x * blockDim.x + threadIdx.x;
    if (idx >= NBATCH * ZDIM) return;
    int b = idx / ZDIM;
    int c = idx - b * ZDIM;
    float v;
    if (c < 9408) {
        v = freq[b * 3136 + (c % 3136)];
    } else if (c < 17600) {
        int cc = c - 9408;                 // cc = d*64 + l
        int d = cc >> 6, l = cc & 63;
        v = fuse[(size_t)seq[b * 64 + l] * 128 + d];
    } else {
        int d = c - 17600;
        v = fuse[(size_t)(n_poi[0] + uid[b]) * 128 + d];
    }
    zout[idx] = v;
    g_zh[idx] = __float2half(v);
}

// ---------------- fp32 -> fp16 weight conversion ----------------
__global__ void convW1_kernel(const float* __restrict__ W1) {
    size_t i = (size_t)blockIdx.x * blockDim.x + threadIdx.x;   // pair index
    const size_t N = (size_t)ZDIM * HID / 2;
    if (i >= N) return;
    float2 v = ((const float2*)W1)[i];
    ((__half2*)g_W1h)[i] = __floats2half2_rn(v.x, v.y);
}

__global__ void convW2_kernel(const float* __restrict__ W2) {
    size_t i = (size_t)blockIdx.x * blockDim.x + threadIdx.x;   // pair index over padded layout
    const size_t N = (size_t)HID * N2PAD / 2;
    if (i >= N) return;
    int k  = (int)(i / (N2PAD / 2));
    int np = (int)(i % (N2PAD / 2));
    int n  = np * 2;
    float2 v;
    if (n < ZDIM) v = *(const float2*)(W2 + (size_t)k * ZDIM + n);
    else          v = make_float2(0.0f, 0.0f);
    ((__half2*)g_W2h)[i] = __floats2half2_rn(v.x, v.y);
}

// ---------------- GEMM: 128x128 CTA tile, BK=64, 3-stage cp.async, mma.sync fp16 ----------------
#define STAGES 3
#define SMEM_BYTES (STAGES * (128 * 64 + 64 * 128) * 2)   // 98304 B

__device__ __forceinline__ uint32_t s2u(const void* p) {
    return (uint32_t)__cvta_generic_to_shared(p);
}
__device__ __forceinline__ void cp16(uint32_t dst, const void* src) {
    asm volatile("cp.async.cg.shared.global [%0],[%1],16;\n" :: "r"(dst), "l"(src));
}

// MODE 0: h_partial = zh @ W1h  (split-K over blockIdx.y, fp32 partials to g_hpart)
// MODE 1: z += h @ W2h + b2     (reads/writes zio=d_out fp32, refreshes g_zh fp16)
template <int MODE>
__global__ __launch_bounds__(256, 1) void gemm_kernel(const float* __restrict__ bias,
                                                      float* __restrict__ zio) {
    extern __shared__ __half sm[];
    __half* As = sm;                          // [STAGES][128*64]
    __half* Bs = sm + STAGES * 128 * 64;      // [STAGES][64*128]

    const __half* A;
    const __half* B;
    int lda, ldb, kb0, nkb;
    const int n0 = blockIdx.x * 128;
    if (MODE == 0) {
        A = g_zh;  B = g_W1h;  lda = ZDIM; ldb = HID;
        kb0 = blockIdx.y * KCHUNK;
        nkb = min(KCHUNK, KB1 - kb0);
    } else {
        A = g_h;   B = g_W2h;  lda = HID;  ldb = N2PAD;
        kb0 = 0;   nkb = KB2;
    }

    const int tid = threadIdx.x, lane = tid & 31, warp = tid >> 5;
    const int wm = warp >> 2;     // 0..1  (M direction, 64 rows each)
    const int wn = warp & 3;      // 0..3  (N direction, 32 cols each)

    float acc[4][4][4];
#pragma unroll
    for (int f = 0; f < 4; f++)
#pragma unroll
        for (int t = 0; t < 4; t++)
#pragma unroll
            for (int i = 0; i < 4; i++) acc[f][t][i] = 0.0f;

    auto load_stage = [&](int st, int kb) {
        __half* as = As + st * (128 * 64);
        __half* bs = Bs + st * (64 * 128);
#pragma unroll
        for (int i = 0; i < 4; i++) {
            int idx = tid + i * 256;
            int m = idx >> 3, c = idx & 7;
            cp16(s2u(as + m * 64 + ((c ^ (m & 7)) << 3)),
                 A + (size_t)m * lda + (size_t)kb * 64 + c * 8);
        }
#pragma unroll
        for (int i = 0; i < 4; i++) {
            int idx = tid + i * 256;
            int k = idx >> 4, c = idx & 15;
            cp16(s2u(bs + k * 128 + ((c ^ (k & 7)) << 3)),
                 B + (size_t)(kb * 64 + k) * ldb + n0 + c * 8);
        }
    };

    // prologue: stages 0..STAGES-2
#pragma unroll
    for (int s = 0; s < STAGES - 1; s++) {
        if (s < nkb) load_stage(s, kb0 + s);
        asm volatile("cp.async.commit_group;\n");
    }

    for (int kb = 0; kb < nkb; kb++) {
        asm volatile("cp.async.wait_group %0;\n" :: "n"(STAGES - 2));
        __syncthreads();
        if (kb + STAGES - 1 < nkb) load_stage((kb + STAGES - 1) % STAGES, kb0 + kb + STAGES - 1);
        asm volatile("cp.async.commit_group;\n");

        const __half* as = As + (kb % STAGES) * (128 * 64);
        const __half* bs = Bs + (kb % STAGES) * (64 * 128);

#pragma unroll
        for (int ks = 0; ks < 4; ks++) {
            uint32_t a[4][4], bf[4][2];
#pragma unroll
            for (int f = 0; f < 4; f++) {
                int m  = wm * 64 + f * 16 + (lane & 15);
                int ch = ks * 2 + (lane >> 4);
                uint32_t addr = s2u(as + m * 64 + ((ch ^ (m & 7)) << 3));
                asm volatile("ldmatrix.sync.aligned.m8n8.x4.shared.b16 {%0,%1,%2,%3},[%4];\n"
                             : "=r"(a[f][0]), "=r"(a[f][1]), "=r"(a[f][2]), "=r"(a[f][3])
                             : "r"(addr));
            }
#pragma unroll
            for (int h = 0; h < 2; h++) {
                int kr = ks * 16 + (lane & 15);
                int nc = ((wn * 32 + h * 16) >> 3) + (lane >> 4);
                uint32_t addr = s2u(bs + kr * 128 + ((nc ^ (kr & 7)) << 3));
                uint32_t r0, r1, r2, r3;
                asm volatile("ldmatrix.sync.aligned.m8n8.x4.trans.shared.b16 {%0,%1,%2,%3},[%4];\n"
                             : "=r"(r0), "=r"(r1), "=r"(r2), "=r"(r3) : "r"(addr));
                bf[h * 2][0] = r0; bf[h * 2][1] = r1;
                bf[h * 2 + 1][0] = r2; bf[h * 2 + 1][1] = r3;
            }
#pragma unroll
            for (int f = 0; f < 4; f++)
#pragma unroll
                for (int t = 0; t < 4; t++) {
                    asm volatile(
                        "mma.sync.aligned.m16n8k16.row.col.f32.f16.f16.f32 "
                        "{%0,%1,%2,%3},{%4,%5,%6,%7},{%8,%9},{%0,%1,%2,%3};\n"
                        : "+f"(acc[f][t][0]), "+f"(acc[f][t][1]),
                          "+f"(acc[f][t][2]), "+f"(acc[f][t][3])
                        : "r"(a[f][0]), "r"(a[f][1]), "r"(a[f][2]), "r"(a[f][3]),
                          "r"(bf[t][0]), "r"(bf[t][1]));
                }
        }
    }

    if (MODE == 0) {
        float* hp = g_hpart + (size_t)blockIdx.y * NBATCH * HID;
#pragma unroll
        for (int f = 0; f < 4; f++) {
            int row = wm * 64 + f * 16 + (lane >> 2);
#pragma unroll
            for (int t = 0; t < 4; t++) {
                int col = n0 + wn * 32 + t * 8 + ((lane & 3) << 1);
                *(float2*)(hp + (size_t)row * HID + col)       = make_float2(acc[f][t][0], acc[f][t][1]);
                *(float2*)(hp + (size_t)(row + 8) * HID + col) = make_float2(acc[f][t][2], acc[f][t][3]);
            }
        }
    } else {
#pragma unroll
        for (int f = 0; f < 4; f++) {
            int row = wm * 64 + f * 16 + (lane >> 2);
#pragma unroll
            for (int t = 0; t < 4; t++) {
                int col = n0 + wn * 32 + t * 8 + ((lane & 3) << 1);
                if (col < ZDIM) {
                    float b0v = bias[col], b1v = bias[col + 1];
                    size_t o0 = (size_t)row * ZDIM + col;
                    float z0 = zio[o0]     + acc[f][t][0] + b0v;
                    float z1 = zio[o0 + 1] + acc[f][t][1] + b1v;
                    zio[o0] = z0; zio[o0 + 1] = z1;
                    *(__half2*)(g_zh + o0) = __floats2half2_rn(z0, z1);
                    size_t o1 = (size_t)(row + 8) * ZDIM + col;
                    float z2 = zio[o1]     + acc[f][t][2] + b0v;
                    float z3 = zio[o1 + 1] + acc[f][t][3] + b1v;
                    zio[o1] = z2; zio[o1 + 1] = z3;
                    *(__half2*)(g_zh + o1) = __floats2half2_rn(z2, z3);
                }
            }
        }
    }
}

// ---------------- split-K reduce + bias + time-embedding tail + tanh ----------------
__global__ void reduce_tanh_kernel(const float* __restrict__ W1, const float* __restrict__ b1, int t) {
    int idx = blockIdx.x * 256 + threadIdx.x;      // < 128*4096
    int b = idx >> 12, n = idx & 4095;
    float s = g_hpart[idx]
            + g_hpart[idx + 1 * NBATCH * HID]
            + g_hpart[idx + 2 * NBATCH * HID]
            + g_hpart[idx + 3 * NBATCH * HID]
            + b1[n];
    const float* e0 = g_emb + (t * NBATCH + b) * 6;
    const float* e1 = e0 + NBATCH * 6;
#pragma unroll
    for (int j = 0; j < 6; j++) s += e0[j] * W1[(size_t)(ZDIM + j) * HID + n];
#pragma unroll
    for (int j = 0; j < 6; j++) s += e1[j] * W1[(size_t)(ZDIM + 6 + j) * HID + n];
    g_h[idx] = __float2half(tanhf(s));
}

// ---------------- launcher ----------------
extern "C" void kernel_launch(void* const* d_in, const int* in_sizes, int n_in,
                              void* d_out, int out_size) {
    const float* input_freq = (const float*)d_in[0];
    const int*   input_seq  = (const int*)  d_in[1];
    const int*   uid        = (const int*)  d_in[2];
    const float* cur_time   = (const float*)d_in[3];
    const float* tar_time   = (const float*)d_in[4];
    const float* fuse       = (const float*)d_in[5];
    const float* W1         = (const float*)d_in[6];
    const float* b1         = (const float*)d_in[7];
    const float* W2         = (const float*)d_in[8];
    const float* b2         = (const float*)d_in[9];
    const int*   n_poi      = (const int*)  d_in[10];
    float* z = (float*)d_out;

    cudaFuncSetAttribute(gemm_kernel<0>, cudaFuncAttributeMaxDynamicSharedMemorySize, SMEM_BYTES);
    cudaFuncSetAttribute(gemm_kernel<1>, cudaFuncAttributeMaxDynamicSharedMemorySize, SMEM_BYTES);

    emb_kernel<<<1, 128>>>(cur_time, tar_time);
    z0_kernel<<<(NBATCH * ZDIM + 511) / 512, 512>>>(input_freq, input_seq, uid, fuse, n_poi, z);

    {   // weight conversion, once per launch
        size_t n1 = (size_t)ZDIM * HID / 2;
        size_t n2 = (size_t)HID * N2PAD / 2;
        convW1_kernel<<<(unsigned)((n1 + 255) / 256), 256>>>(W1);
        convW2_kernel<<<(unsigned)((n2 + 255) / 256), 256>>>(W2);
    }

    for (int t = 0; t < NSTEPS; t++) {
        gemm_kernel<0><<<dim3(HID / 128, SPLITK), 256, SMEM_BYTES>>>(nullptr, nullptr);
        reduce_tanh_kernel<<<NBATCH * HID / 256, 256>>>(W1, b1, t);
        gemm_kernel<1><<<dim3(N2PAD / 128, 1), 256, SMEM_BYTES>>>(b2, z);
    }
}

// round 8
// speedup vs baseline: 1.1762x; 1.1762x over previous
#include <cuda_runtime.h>
#include <cuda_fp16.h>
#include <math.h>
#include <stdint.h>

// ---------------- problem constants ----------------
#define ZDIM   17728      // 3*56*56 + 64*128 + 128
#define HID    4096
#define NBATCH 128
#define N2PAD  17792      // 139*128, padded N for GEMM2
#define NSTEPS 11
#define KB1    277        // 17728/64 K-tiles for GEMM1
#define KB2    64         // 4096/64  K-tiles for GEMM2
#define SPLITK1 8
#define KCHUNK1 35        // ceil(277/8); last chunk = 32
#define SPLITK2 2
#define KCHUNK2 32

// ---------------- device scratch (no allocs allowed) ----------------
__device__ __half g_W1h[(size_t)ZDIM * HID];       // W1 fp16, [k][n] K-major rows
__device__ __half g_W2h[(size_t)HID * N2PAD];      // W2 fp16, [k][n], N padded w/ zeros
__device__ __half g_zh [(size_t)NBATCH * ZDIM];    // fp16 activations z
__device__ __half g_h  [(size_t)NBATCH * HID];     // fp16 hidden h
__device__ float  g_hpart [(size_t)SPLITK1 * NBATCH * HID];    // 16 MB GEMM1 partials
__device__ float  g_h2part[(size_t)SPLITK2 * NBATCH * N2PAD];  // 18 MB GEMM2 partials
__device__ float  g_emb[12 * NBATCH * 6];

// ---------------- time grid + embedding ----------------
__global__ void emb_kernel(const float* __restrict__ cur, const float* __restrict__ tar) {
    int b = threadIdx.x;
    if (b >= NBATCH) return;
    const float P[3] = {24.0f, 7.0f, 365.0f};
    float tc[3];
    for (int j = 0; j < 3; j++) tc[j] = cur[b * 3 + j];
    int r = 0;
    for (int j = 0; j < 3; j++) {
        float s = cur[b * 3 + j], e = tar[b * 3 + j];
        bool wrap = s > e;
        float ea = wrap ? e + P[j] : e;
        for (int k = 0; k < 4; k++) {
            float frac = (float)k / 3.0f;
            float inter = s + (ea - s) * frac;
            if (wrap) inter = fmodf(inter, P[j]);
            tc[j] = inter;
            for (int jj = 0; jj < 3; jj++) {
                float ph = 6.2831853071795864769f * tc[jj] / P[jj];
                g_emb[(r * NBATCH + b) * 6 + jj]     = sinf(ph);
                g_emb[(r * NBATCH + b) * 6 + 3 + jj] = cosf(ph);
            }
            r++;
        }
    }
}

// ---------------- z0 build ----------------
__global__ void z0_kernel(const float* __restrict__ freq, const int* __restrict__ seq,
                          const int* __restrict__ uid, const float* __restrict__ fuse,
                          const int* __restrict__ n_poi, float* __restrict__ zout) {
    int idx = blockIdx.x * blockDim.x + threadIdx.x;
    if (idx >= NBATCH * ZDIM) return;
    int b = idx / ZDIM;
    int c = idx - b * ZDIM;
    float v;
    if (c < 9408) {
        v = freq[b * 3136 + (c % 3136)];
    } else if (c < 17600) {
        int cc = c - 9408;
        int d = cc >> 6, l = cc & 63;
        v = fuse[(size_t)seq[b * 64 + l] * 128 + d];
    } else {
        int d = c - 17600;
        v = fuse[(size_t)(n_poi[0] + uid[b]) * 128 + d];
    }
    zout[idx] = v;
    g_zh[idx] = __float2half(v);
}

// ---------------- fp32 -> fp16 weight conversion (vectorized) ----------------
__global__ void convW1_kernel(const float* __restrict__ W1) {
    size_t i = (size_t)blockIdx.x * blockDim.x + threadIdx.x;   // quad index
    const size_t N = (size_t)ZDIM * HID / 4;
    if (i >= N) return;
    float4 v = ((const float4*)W1)[i];
    __half2* d = (__half2*)g_W1h + i * 2;
    d[0] = __floats2half2_rn(v.x, v.y);
    d[1] = __floats2half2_rn(v.z, v.w);
}

__global__ void convW2_kernel(const float* __restrict__ W2) {
    size_t i = (size_t)blockIdx.x * blockDim.x + threadIdx.x;   // quad index over padded layout
    const size_t N = (size_t)HID * N2PAD / 4;
    if (i >= N) return;
    int k = (int)(i / (N2PAD / 4));
    int n = (int)(i % (N2PAD / 4)) * 4;
    float4 v;
    if (n < ZDIM) v = *(const float4*)(W2 + (size_t)k * ZDIM + n);   // ZDIM%4==0
    else          v = make_float4(0.f, 0.f, 0.f, 0.f);
    __half2* d = (__half2*)g_W2h + i * 2;
    d[0] = __floats2half2_rn(v.x, v.y);
    d[1] = __floats2half2_rn(v.z, v.w);
}

// ---------------- GEMM: 128x128 CTA tile, BK=64, 3-stage cp.async, mma.sync fp16 ----------------
#define STAGES 3
#define SMEM_BYTES (STAGES * (128 * 64 + 64 * 128) * 2)   // 98304 B -> 2 CTAs/SM

__device__ __forceinline__ uint32_t s2u(const void* p) {
    return (uint32_t)__cvta_generic_to_shared(p);
}
__device__ __forceinline__ void cp16(uint32_t dst, const void* src) {
    asm volatile("cp.async.cg.shared.global [%0],[%1],16;\n" :: "r"(dst), "l"(src));
}

// MODE 0: g_hpart [split] = zh @ W1h   (split-K over blockIdx.y, 8 ways)
// MODE 1: g_h2part[split] = h  @ W2h   (split-K over blockIdx.y, 2 ways)
template <int MODE>
__global__ __launch_bounds__(256, 2) void gemm_kernel() {
    extern __shared__ __half sm[];
    __half* As = sm;                          // [STAGES][128*64]
    __half* Bs = sm + STAGES * 128 * 64;      // [STAGES][64*128]

    const __half* A;
    const __half* B;
    int lda, ldb, kb0, nkb, ldo;
    float* part;
    const int n0 = blockIdx.x * 128;
    if (MODE == 0) {
        A = g_zh;  B = g_W1h;  lda = ZDIM; ldb = HID;  ldo = HID;
        kb0 = blockIdx.y * KCHUNK1;
        nkb = min(KCHUNK1, KB1 - kb0);
        part = g_hpart + (size_t)blockIdx.y * NBATCH * HID;
    } else {
        A = g_h;   B = g_W2h;  lda = HID;  ldb = N2PAD; ldo = N2PAD;
        kb0 = blockIdx.y * KCHUNK2;
        nkb = KCHUNK2;
        part = g_h2part + (size_t)blockIdx.y * NBATCH * N2PAD;
    }

    const int tid = threadIdx.x, lane = tid & 31, warp = tid >> 5;
    const int wm = warp >> 2;     // 0..1  (M direction, 64 rows each)
    const int wn = warp & 3;      // 0..3  (N direction, 32 cols each)

    float acc[4][4][4];
#pragma unroll
    for (int f = 0; f < 4; f++)
#pragma unroll
        for (int t = 0; t < 4; t++)
#pragma unroll
            for (int i = 0; i < 4; i++) acc[f][t][i] = 0.0f;

    auto load_stage = [&](int st, int kb) {
        __half* as = As + st * (128 * 64);
        __half* bs = Bs + st * (64 * 128);
#pragma unroll
        for (int i = 0; i < 4; i++) {
            int idx = tid + i * 256;
            int m = idx >> 3, c = idx & 7;
            cp16(s2u(as + m * 64 + ((c ^ (m & 7)) << 3)),
                 A + (size_t)m * lda + (size_t)kb * 64 + c * 8);
        }
#pragma unroll
        for (int i = 0; i < 4; i++) {
            int idx = tid + i * 256;
            int k = idx >> 4, c = idx & 15;
            cp16(s2u(bs + k * 128 + ((c ^ (k & 7)) << 3)),
                 B + (size_t)(kb * 64 + k) * ldb + n0 + c * 8);
        }
    };

    // prologue: stages 0..STAGES-2
#pragma unroll
    for (int s = 0; s < STAGES - 1; s++) {
        if (s < nkb) load_stage(s, kb0 + s);
        asm volatile("cp.async.commit_group;\n");
    }

    for (int kb = 0; kb < nkb; kb++) {
        asm volatile("cp.async.wait_group %0;\n" :: "n"(STAGES - 2));
        __syncthreads();
        if (kb + STAGES - 1 < nkb) load_stage((kb + STAGES - 1) % STAGES, kb0 + kb + STAGES - 1);
        asm volatile("cp.async.commit_group;\n");

        const __half* as = As + (kb % STAGES) * (128 * 64);
        const __half* bs = Bs + (kb % STAGES) * (64 * 128);

#pragma unroll
        for (int ks = 0; ks < 4; ks++) {
            uint32_t a[4][4], bf[4][2];
#pragma unroll
            for (int f = 0; f < 4; f++) {
                int m  = wm * 64 + f * 16 + (lane & 15);
                int ch = ks * 2 + (lane >> 4);
                uint32_t addr = s2u(as + m * 64 + ((ch ^ (m & 7)) << 3));
                asm volatile("ldmatrix.sync.aligned.m8n8.x4.shared.b16 {%0,%1,%2,%3},[%4];\n"
                             : "=r"(a[f][0]), "=r"(a[f][1]), "=r"(a[f][2]), "=r"(a[f][3])
                             : "r"(addr));
            }
#pragma unroll
            for (int h = 0; h < 2; h++) {
                int kr = ks * 16 + (lane & 15);
                int nc = ((wn * 32 + h * 16) >> 3) + (lane >> 4);
                uint32_t addr = s2u(bs + kr * 128 + ((nc ^ (kr & 7)) << 3));
                uint32_t r0, r1, r2, r3;
                asm volatile("ldmatrix.sync.aligned.m8n8.x4.trans.shared.b16 {%0,%1,%2,%3},[%4];\n"
                             : "=r"(r0), "=r"(r1), "=r"(r2), "=r"(r3) : "r"(addr));
                bf[h * 2][0] = r0; bf[h * 2][1] = r1;
                bf[h * 2 + 1][0] = r2; bf[h * 2 + 1][1] = r3;
            }
#pragma unroll
            for (int f = 0; f < 4; f++)
#pragma unroll
                for (int t = 0; t < 4; t++) {
                    asm volatile(
                        "mma.sync.aligned.m16n8k16.row.col.f32.f16.f16.f32 "
                        "{%0,%1,%2,%3},{%4,%5,%6,%7},{%8,%9},{%0,%1,%2,%3};\n"
                        : "+f"(acc[f][t][0]), "+f"(acc[f][t][1]),
                          "+f"(acc[f][t][2]), "+f"(acc[f][t][3])
                        : "r"(a[f][0]), "r"(a[f][1]), "r"(a[f][2]), "r"(a[f][3]),
                          "r"(bf[t][0]), "r"(bf[t][1]));
                }
        }
    }

    // epilogue: fp32 partials
#pragma unroll
    for (int f = 0; f < 4; f++) {
        int row = wm * 64 + f * 16 + (lane >> 2);
#pragma unroll
        for (int t = 0; t < 4; t++) {
            int col = n0 + wn * 32 + t * 8 + ((lane & 3) << 1);
            *(float2*)(part + (size_t)row * ldo + col)       = make_float2(acc[f][t][0], acc[f][t][1]);
            *(float2*)(part + (size_t)(row + 8) * ldo + col) = make_float2(acc[f][t][2], acc[f][t][3]);
        }
    }
}

// ---------------- GEMM1 reduce + bias + time-embedding tail + tanh ----------------
__global__ void reduce_tanh_kernel(const float* __restrict__ W1, const float* __restrict__ b1, int t) {
    int idx = blockIdx.x * 256 + threadIdx.x;      // < 128*4096
    int b = idx >> 12, n = idx & 4095;
    float s = b1[n];
#pragma unroll
    for (int p = 0; p < SPLITK1; p++)
        s += g_hpart[(size_t)p * NBATCH * HID + idx];
    const float* e0 = g_emb + (t * NBATCH + b) * 6;
    const float* e1 = e0 + NBATCH * 6;
#pragma unroll
    for (int j = 0; j < 6; j++) s += e0[j] * W1[(size_t)(ZDIM + j) * HID + n];
#pragma unroll
    for (int j = 0; j < 6; j++) s += e1[j] * W1[(size_t)(ZDIM + 6 + j) * HID + n];
    g_h[idx] = __float2half(tanhf(s));
}

// ---------------- GEMM2 reduce: z += p0 + p1 + b2, refresh fp16 z ----------------
__global__ void zupdate_kernel(const float* __restrict__ b2, float* __restrict__ z) {
    int idx = blockIdx.x * 256 + threadIdx.x;
    if (idx >= NBATCH * ZDIM) return;
    int row = idx / ZDIM;
    int col = idx - row * ZDIM;
    size_t po = (size_t)row * N2PAD + col;
    float v = z[idx] + b2[col]
            + g_h2part[po]
            + g_h2part[(size_t)NBATCH * N2PAD + po];
    z[idx] = v;
    g_zh[idx] = __float2half(v);
}

// ---------------- launcher ----------------
extern "C" void kernel_launch(void* const* d_in, const int* in_sizes, int n_in,
                              void* d_out, int out_size) {
    const float* input_freq = (const float*)d_in[0];
    const int*   input_seq  = (const int*)  d_in[1];
    const int*   uid        = (const int*)  d_in[2];
    const float* cur_time   = (const float*)d_in[3];
    const float* tar_time   = (const float*)d_in[4];
    const float* fuse       = (const float*)d_in[5];
    const float* W1         = (const float*)d_in[6];
    const float* b1         = (const float*)d_in[7];
    const float* W2         = (const float*)d_in[8];
    const float* b2         = (const float*)d_in[9];
    const int*   n_poi      = (const int*)  d_in[10];
    float* z = (float*)d_out;

    cudaFuncSetAttribute(gemm_kernel<0>, cudaFuncAttributeMaxDynamicSharedMemorySize, SMEM_BYTES);
    cudaFuncSetAttribute(gemm_kernel<1>, cudaFuncAttributeMaxDynamicSharedMemorySize, SMEM_BYTES);

    emb_kernel<<<1, 128>>>(cur_time, tar_time);
    z0_kernel<<<(NBATCH * ZDIM + 511) / 512, 512>>>(input_freq, input_seq, uid, fuse, n_poi, z);

    {   // weight conversion, once per launch (vectorized)
        size_t n1 = (size_t)ZDIM * HID / 4;
        size_t n2 = (size_t)HID * N2PAD / 4;
        convW1_kernel<<<(unsigned)((n1 + 255) / 256), 256>>>(W1);
        convW2_kernel<<<(unsigned)((n2 + 255) / 256), 256>>>(W2);
    }

    for (int t = 0; t < NSTEPS; t++) {
        gemm_kernel<0><<<dim3(HID / 128, SPLITK1), 256, SMEM_BYTES>>>();
        reduce_tanh_kernel<<<NBATCH * HID / 256, 256>>>(W1, b1, t);
        gemm_kernel<1><<<dim3(N2PAD / 128, SPLITK2), 256, SMEM_BYTES>>>();
        zupdate_kernel<<<(NBATCH * ZDIM + 255) / 256, 256>>>(b2, z);
    }
}

// round 9
// speedup vs baseline: 1.2231x; 1.0399x over previous
#include <cuda_runtime.h>
#include <cuda_fp16.h>
#include <math.h>
#include <stdint.h>

// ---------------- problem constants ----------------
#define ZDIM   17728      // 3*56*56 + 64*128 + 128
#define ZPAD   17920      // 280*64 : padded K for GEMM1 (uniform split-K chunks)
#define HID    4096
#define NBATCH 128
#define N2PAD  17792      // 139*128, padded N for GEMM2
#define NSTEPS 11
#define SPLITK1 8
#define NKB1   35         // 280/8 K-tiles per split group (compile-time)
#define SPLITK2 2
#define NKB2   32         // 64/2

// ---------------- device scratch (no allocs allowed) ----------------
__device__ __half g_W1h[(size_t)ZPAD * HID];       // W1 fp16 [k][n], k padded w/ zeros
__device__ __half g_W2h[(size_t)HID * N2PAD];      // W2 fp16 [k][n], n padded w/ zeros
__device__ __half g_zh [(size_t)NBATCH * ZPAD];    // fp16 z, k-padded w/ zeros
__device__ __half g_h  [(size_t)NBATCH * HID];     // fp16 hidden h
__device__ float  g_hpart [(size_t)SPLITK1 * NBATCH * HID];
__device__ float  g_h2part[(size_t)SPLITK2 * NBATCH * N2PAD];
__device__ float  g_emb[12 * NBATCH * 6];

// ---------------- time grid + embedding ----------------
__global__ void emb_kernel(const float* __restrict__ cur, const float* __restrict__ tar) {
    int b = threadIdx.x;
    if (b >= NBATCH) return;
    const float P[3] = {24.0f, 7.0f, 365.0f};
    float tc[3];
    for (int j = 0; j < 3; j++) tc[j] = cur[b * 3 + j];
    int r = 0;
    for (int j = 0; j < 3; j++) {
        float s = cur[b * 3 + j], e = tar[b * 3 + j];
        bool wrap = s > e;
        float ea = wrap ? e + P[j] : e;
        for (int k = 0; k < 4; k++) {
            float frac = (float)k / 3.0f;
            float inter = s + (ea - s) * frac;
            if (wrap) inter = fmodf(inter, P[j]);
            tc[j] = inter;
            for (int jj = 0; jj < 3; jj++) {
                float ph = 6.2831853071795864769f * tc[jj] / P[jj];
                g_emb[(r * NBATCH + b) * 6 + jj]     = sinf(ph);
                g_emb[(r * NBATCH + b) * 6 + 3 + jj] = cosf(ph);
            }
            r++;
        }
    }
}

// ---------------- z0 build (stride ZPAD for fp16 copy) ----------------
__global__ void z0_kernel(const float* __restrict__ freq, const int* __restrict__ seq,
                          const int* __restrict__ uid, const float* __restrict__ fuse,
                          const int* __restrict__ n_poi, float* __restrict__ zout) {
    int idx = blockIdx.x * blockDim.x + threadIdx.x;
    if (idx >= NBATCH * ZDIM) return;
    int b = idx / ZDIM;
    int c = idx - b * ZDIM;
    float v;
    if (c < 9408) {
        v = freq[b * 3136 + (c % 3136)];
    } else if (c < 17600) {
        int cc = c - 9408;
        int d = cc >> 6, l = cc & 63;
        v = fuse[(size_t)seq[b * 64 + l] * 128 + d];
    } else {
        int d = c - 17600;
        v = fuse[(size_t)(n_poi[0] + uid[b]) * 128 + d];
    }
    zout[idx] = v;
    g_zh[(size_t)b * ZPAD + c] = __float2half(v);
}

// zero the K-pad region of g_zh (cols [ZDIM, ZPAD)) — idempotent
__global__ void zpad_kernel() {
    int i = blockIdx.x * 256 + threadIdx.x;     // < 128 * 96  (half2 units)
    if (i >= NBATCH * (ZPAD - ZDIM) / 2) return;
    int b = i / ((ZPAD - ZDIM) / 2);
    int c = (i % ((ZPAD - ZDIM) / 2)) * 2;
    *(__half2*)(g_zh + (size_t)b * ZPAD + ZDIM + c) = __floats2half2_rn(0.f, 0.f);
}

// ---------------- fp32 -> fp16 weight conversion (vectorized) ----------------
__global__ void convW1_kernel(const float* __restrict__ W1) {
    size_t i = (size_t)blockIdx.x * blockDim.x + threadIdx.x;   // quad over [ZPAD][HID]
    const size_t N = (size_t)ZPAD * HID / 4;
    if (i >= N) return;
    int k = (int)(i >> 10);                  // HID/4 = 1024
    int n = (int)(i & 1023) * 4;
    float4 v;
    if (k < ZDIM) v = *(const float4*)(W1 + (size_t)k * HID + n);
    else          v = make_float4(0.f, 0.f, 0.f, 0.f);
    __half2* d = (__half2*)g_W1h + i * 2;
    d[0] = __floats2half2_rn(v.x, v.y);
    d[1] = __floats2half2_rn(v.z, v.w);
}

__global__ void convW2_kernel(const float* __restrict__ W2) {
    size_t i = (size_t)blockIdx.x * blockDim.x + threadIdx.x;   // quad over [HID][N2PAD]
    const size_t N = (size_t)HID * N2PAD / 4;
    if (i >= N) return;
    int k = (int)(i / (N2PAD / 4));
    int n = (int)(i % (N2PAD / 4)) * 4;
    float4 v;
    if (n < ZDIM) v = *(const float4*)(W2 + (size_t)k * ZDIM + n);   // ZDIM%4==0
    else          v = make_float4(0.f, 0.f, 0.f, 0.f);
    __half2* d = (__half2*)g_W2h + i * 2;
    d[0] = __floats2half2_rn(v.x, v.y);
    d[1] = __floats2half2_rn(v.z, v.w);
}

// ---------------- GEMM: 128x128 CTA tile, BK=64, 3-stage cp.async, mma.sync fp16 ----------------
// smem stage layout: stage s at offset s*32768; A tile at +0 (16KB), B tile at +16384 (16KB)
#define STAGEB 32768
#define SMEM_BYTES (3 * STAGEB)    // 98304 -> 2 CTAs/SM

__device__ __forceinline__ uint32_t s2u(const void* p) {
    return (uint32_t)__cvta_generic_to_shared(p);
}
__device__ __forceinline__ void cp16(uint32_t dst, const void* src) {
    asm volatile("cp.async.cg.shared.global [%0],[%1],16;\n" :: "r"(dst), "l"(src));
}

// MODE 0: g_hpart [split] = zh @ W1h   (split-K 8, NKB=35)
// MODE 1: g_h2part[split] = h  @ W2h   (split-K 2, NKB=32)
template <int MODE>
__global__ __launch_bounds__(256, 2) void gemm_kernel() {
    constexpr int LDA = (MODE == 0) ? ZPAD : HID;
    constexpr int LDB = (MODE == 0) ? HID  : N2PAD;
    constexpr int LDO = (MODE == 0) ? HID  : N2PAD;
    constexpr int NKB = (MODE == 0) ? NKB1 : NKB2;

    extern __shared__ char sm[];
    const uint32_t smb = s2u(sm);
    const int tid = threadIdx.x, lane = tid & 31, warp = tid >> 5;
    const int wm = warp >> 2, wn = warp & 3;
    const int n0 = blockIdx.x * 128;
    const int kb0 = blockIdx.y * NKB;

    const __half* A = (MODE == 0) ? g_zh : g_h;
    const __half* B = (MODE == 0) ? g_W1h : g_W2h;
    float* part = ((MODE == 0) ? g_hpart : g_h2part)
                + (size_t)blockIdx.y * NBATCH * LDO;

    // ---- hoisted load setup (all strides compile-time) ----
    const int am = tid >> 3, ac = tid & 7;      // A: 128 rows x 8 chunks
    const int bk = tid >> 4, bc = tid & 15;     // B: 64 rows x 16 chunks
    const __half* aptr = A + (size_t)am * LDA + kb0 * 64 + ac * 8;
    const __half* bptr = B + (size_t)(kb0 * 64 + bk) * LDB + n0 + bc * 8;
    const uint32_t aoff = (uint32_t)(am * 128 + ((ac ^ (am & 7)) << 4));          // bytes
    const uint32_t boff = 16384u + (uint32_t)(bk * 256 + ((bc ^ (bk & 7)) << 4)); // bytes

    // ---- hoisted ldmatrix addressing (2 adds per ldmatrix in the loop) ----
    const int hi = lane >> 4, lo7 = lane & 7, lo15 = lane & 15;
    uint32_t baseA[4], swA[4], preB[2];
#pragma unroll
    for (int f = 0; f < 4; f++) baseA[f] = (uint32_t)((wm * 64 + f * 16 + lo15) * 128);
#pragma unroll
    for (int ks = 0; ks < 4; ks++) swA[ks] = (uint32_t)(((ks * 2 + hi) ^ lo7) << 4);
#pragma unroll
    for (int h = 0; h < 2; h++)
        preB[h] = 16384u + (uint32_t)((((wn * 4 + h * 2 + hi) ^ lo7) << 4) + lo15 * 256);

    float acc[4][4][4];
#pragma unroll
    for (int f = 0; f < 4; f++)
#pragma unroll
        for (int t = 0; t < 4; t++)
#pragma unroll
            for (int i = 0; i < 4; i++) acc[f][t][i] = 0.0f;

    auto load_stage = [&](uint32_t stage) {
#pragma unroll
        for (int i = 0; i < 4; i++) {
            cp16(stage + aoff + i * 4096, aptr + i * 32 * LDA);
            cp16(stage + boff + i * 4096, bptr + (size_t)i * 16 * LDB);
        }
        aptr += 64;
        bptr += (size_t)64 * LDB;
    };

    uint32_t s0 = smb, s1 = smb + STAGEB, s2 = smb + 2 * STAGEB;

    // prologue: tiles 0,1 into stages 0,1
    load_stage(s0);
    asm volatile("cp.async.commit_group;\n");
    load_stage(s1);
    asm volatile("cp.async.commit_group;\n");

#pragma unroll 1
    for (int kb = 0; kb < NKB; kb++) {
        asm volatile("cp.async.wait_group %0;\n" :: "n"(1));
        __syncthreads();
        if (kb + 2 < NKB) load_stage(s2);
        asm volatile("cp.async.commit_group;\n");

#pragma unroll
        for (int ks = 0; ks < 4; ks++) {
            uint32_t a[4][4], bf[4][2];
#pragma unroll
            for (int f = 0; f < 4; f++) {
                asm volatile("ldmatrix.sync.aligned.m8n8.x4.shared.b16 {%0,%1,%2,%3},[%4];\n"
                             : "=r"(a[f][0]), "=r"(a[f][1]), "=r"(a[f][2]), "=r"(a[f][3])
                             : "r"(s0 + baseA[f] + swA[ks]));
            }
#pragma unroll
            for (int h = 0; h < 2; h++) {
                uint32_t r0, r1, r2, r3;
                asm volatile("ldmatrix.sync.aligned.m8n8.x4.trans.shared.b16 {%0,%1,%2,%3},[%4];\n"
                             : "=r"(r0), "=r"(r1), "=r"(r2), "=r"(r3)
                             : "r"(s0 + preB[h] + ks * 4096));
                bf[h * 2][0] = r0; bf[h * 2][1] = r1;
                bf[h * 2 + 1][0] = r2; bf[h * 2 + 1][1] = r3;
            }
#pragma unroll
            for (int f = 0; f < 4; f++)
#pragma unroll
                for (int t = 0; t < 4; t++) {
                    asm volatile(
                        "mma.sync.aligned.m16n8k16.row.col.f32.f16.f16.f32 "
                        "{%0,%1,%2,%3},{%4,%5,%6,%7},{%8,%9},{%0,%1,%2,%3};\n"
                        : "+f"(acc[f][t][0]), "+f"(acc[f][t][1]),
                          "+f"(acc[f][t][2]), "+f"(acc[f][t][3])
                        : "r"(a[f][0]), "r"(a[f][1]), "r"(a[f][2]), "r"(a[f][3]),
                          "r"(bf[t][0]), "r"(bf[t][1]));
                }
        }
        // rotate stages: compute kb+1 uses old s1; load target becomes old s0
        uint32_t tmp = s0; s0 = s1; s1 = s2; s2 = tmp;
    }

    // epilogue: fp32 partials
#pragma unroll
    for (int f = 0; f < 4; f++) {
        int row = wm * 64 + f * 16 + (lane >> 2);
#pragma unroll
        for (int t = 0; t < 4; t++) {
            int col = n0 + wn * 32 + t * 8 + ((lane & 3) << 1);
            *(float2*)(part + (size_t)row * LDO + col)       = make_float2(acc[f][t][0], acc[f][t][1]);
            *(float2*)(part + (size_t)(row + 8) * LDO + col) = make_float2(acc[f][t][2], acc[f][t][3]);
        }
    }
}

// ---------------- GEMM1 reduce + bias + time-embedding tail + tanh ----------------
__global__ void reduce_tanh_kernel(const float* __restrict__ W1, const float* __restrict__ b1, int t) {
    int idx = blockIdx.x * 256 + threadIdx.x;      // < 128*4096
    int b = idx >> 12, n = idx & 4095;
    float s = b1[n];
#pragma unroll
    for (int p = 0; p < SPLITK1; p++)
        s += g_hpart[(size_t)p * NBATCH * HID + idx];
    const float* e0 = g_emb + (t * NBATCH + b) * 6;
    const float* e1 = e0 + NBATCH * 6;
#pragma unroll
    for (int j = 0; j < 6; j++) s += e0[j] * W1[(size_t)(ZDIM + j) * HID + n];
#pragma unroll
    for (int j = 0; j < 6; j++) s += e1[j] * W1[(size_t)(ZDIM + 6 + j) * HID + n];
    g_h[idx] = __float2half(tanhf(s));
}

// ---------------- GEMM2 reduce: z += p0 + p1 + b2, refresh fp16 z ----------------
__global__ void zupdate_kernel(const float* __restrict__ b2, float* __restrict__ z) {
    int idx = blockIdx.x * 256 + threadIdx.x;
    if (idx >= NBATCH * ZDIM) return;
    int row = idx / ZDIM;
    int col = idx - row * ZDIM;
    size_t po = (size_t)row * N2PAD + col;
    float v = z[idx] + b2[col]
            + g_h2part[po]
            + g_h2part[(size_t)NBATCH * N2PAD + po];
    z[idx] = v;
    g_zh[(size_t)row * ZPAD + col] = __float2half(v);
}

// ---------------- launcher ----------------
extern "C" void kernel_launch(void* const* d_in, const int* in_sizes, int n_in,
                              void* d_out, int out_size) {
    const float* input_freq = (const float*)d_in[0];
    const int*   input_seq  = (const int*)  d_in[1];
    const int*   uid        = (const int*)  d_in[2];
    const float* cur_time   = (const float*)d_in[3];
    const float* tar_time   = (const float*)d_in[4];
    const float* fuse       = (const float*)d_in[5];
    const float* W1         = (const float*)d_in[6];
    const float* b1         = (const float*)d_in[7];
    const float* W2         = (const float*)d_in[8];
    const float* b2         = (const float*)d_in[9];
    const int*   n_poi      = (const int*)  d_in[10];
    float* z = (float*)d_out;

    cudaFuncSetAttribute(gemm_kernel<0>, cudaFuncAttributeMaxDynamicSharedMemorySize, SMEM_BYTES);
    cudaFuncSetAttribute(gemm_kernel<1>, cudaFuncAttributeMaxDynamicSharedMemorySize, SMEM_BYTES);

    emb_kernel<<<1, 128>>>(cur_time, tar_time);
    z0_kernel<<<(NBATCH * ZDIM + 511) / 512, 512>>>(input_freq, input_seq, uid, fuse, n_poi, z);
    zpad_kernel<<<(NBATCH * (ZPAD - ZDIM) / 2 + 255) / 256, 256>>>();

    {   // weight conversion, once per launch (vectorized)
        size_t n1 = (size_t)ZPAD * HID / 4;
        size_t n2 = (size_t)HID * N2PAD / 4;
        convW1_kernel<<<(unsigned)((n1 + 255) / 256), 256>>>(W1);
        convW2_kernel<<<(unsigned)((n2 + 255) / 256), 256>>>(W2);
    }

    for (int t = 0; t < NSTEPS; t++) {
        gemm_kernel<0><<<dim3(HID / 128, SPLITK1), 256, SMEM_BYTES>>>();
        reduce_tanh_kernel<<<NBATCH * HID / 256, 256>>>(W1, b1, t);
        gemm_kernel<1><<<dim3(N2PAD / 128, SPLITK2), 256, SMEM_BYTES>>>();
        zupdate_kernel<<<(NBATCH * ZDIM + 255) / 256, 256>>>(b2, z);
    }
}

// round 10
// speedup vs baseline: 1.2815x; 1.0477x over previous
#include <cuda_runtime.h>
#include <cuda_fp16.h>
#include <math.h>
#include <stdint.h>

// ---------------- problem constants ----------------
#define ZDIM   17728      // 3*56*56 + 64*128 + 128
#define ZPAD   17920      // 280*64 : padded K for GEMM1 (uniform split-K chunks)
#define HID    4096
#define NBATCH 128
#define N2PAD  17792      // 139*128, padded N for GEMM2
#define NSTEPS 11
#define SPLITK1 8
#define NKB1   35         // 280/8 K-tiles per split group (compile-time)
#define SPLITK2 2
#define NKB2   32         // 64/2

// ---------------- device scratch (no allocs allowed) ----------------
__device__ __half g_W1h[(size_t)ZPAD * HID];       // W1 fp16 [k][n], k padded w/ zeros
__device__ __half g_W2h[(size_t)HID * N2PAD];      // W2 fp16 [k][n], n padded w/ zeros
__device__ __half g_zh [(size_t)NBATCH * ZPAD];    // fp16 z, k-padded w/ zeros
__device__ __half g_h  [(size_t)NBATCH * HID];     // fp16 hidden h
__device__ float  g_hpart [(size_t)SPLITK1 * NBATCH * HID];
__device__ float  g_h2part[(size_t)SPLITK2 * NBATCH * N2PAD];
__device__ float  g_emb[12 * NBATCH * 6];

// ---------------- time grid + embedding ----------------
__global__ void emb_kernel(const float* __restrict__ cur, const float* __restrict__ tar) {
    int b = threadIdx.x;
    if (b >= NBATCH) return;
    const float P[3] = {24.0f, 7.0f, 365.0f};
    float tc[3];
    for (int j = 0; j < 3; j++) tc[j] = cur[b * 3 + j];
    int r = 0;
    for (int j = 0; j < 3; j++) {
        float s = cur[b * 3 + j], e = tar[b * 3 + j];
        bool wrap = s > e;
        float ea = wrap ? e + P[j] : e;
        for (int k = 0; k < 4; k++) {
            float frac = (float)k / 3.0f;
            float inter = s + (ea - s) * frac;
            if (wrap) inter = fmodf(inter, P[j]);
            tc[j] = inter;
            for (int jj = 0; jj < 3; jj++) {
                float ph = 6.2831853071795864769f * tc[jj] / P[jj];
                g_emb[(r * NBATCH + b) * 6 + jj]     = sinf(ph);
                g_emb[(r * NBATCH + b) * 6 + 3 + jj] = cosf(ph);
            }
            r++;
        }
    }
}

// ---------------- z0 build (stride ZPAD for fp16 copy) ----------------
__global__ void z0_kernel(const float* __restrict__ freq, const int* __restrict__ seq,
                          const int* __restrict__ uid, const float* __restrict__ fuse,
                          const int* __restrict__ n_poi, float* __restrict__ zout) {
    int idx = blockIdx.x * blockDim.x + threadIdx.x;
    if (idx >= NBATCH * ZDIM) return;
    int b = idx / ZDIM;
    int c = idx - b * ZDIM;
    float v;
    if (c < 9408) {
        v = freq[b * 3136 + (c % 3136)];
    } else if (c < 17600) {
        int cc = c - 9408;
        int d = cc >> 6, l = cc & 63;
        v = fuse[(size_t)seq[b * 64 + l] * 128 + d];
    } else {
        int d = c - 17600;
        v = fuse[(size_t)(n_poi[0] + uid[b]) * 128 + d];
    }
    zout[idx] = v;
    g_zh[(size_t)b * ZPAD + c] = __float2half(v);
}

// zero the K-pad region of g_zh (cols [ZDIM, ZPAD)) — idempotent
__global__ void zpad_kernel() {
    int i = blockIdx.x * 256 + threadIdx.x;     // < 128 * 96  (half2 units)
    if (i >= NBATCH * (ZPAD - ZDIM) / 2) return;
    int b = i / ((ZPAD - ZDIM) / 2);
    int c = (i % ((ZPAD - ZDIM) / 2)) * 2;
    *(__half2*)(g_zh + (size_t)b * ZPAD + ZDIM + c) = __floats2half2_rn(0.f, 0.f);
}

// ---------------- fp32 -> fp16 weight conversion (8 floats/thread, 16B stores) ----------------
__global__ void convW1_kernel(const float* __restrict__ W1) {
    size_t i = (size_t)blockIdx.x * blockDim.x + threadIdx.x;   // oct over [ZPAD][HID]
    const size_t N = (size_t)ZPAD * HID / 8;
    if (i >= N) return;
    int k = (int)(i >> 9);                   // HID/8 = 512
    int n = (int)(i & 511) * 8;
    float4 v0, v1;
    if (k < ZDIM) {
        const float4* s = (const float4*)(W1 + (size_t)k * HID + n);
        v0 = s[0]; v1 = s[1];
    } else {
        v0 = v1 = make_float4(0.f, 0.f, 0.f, 0.f);
    }
    union { __half2 h[4]; uint4 u; } o;
    o.h[0] = __floats2half2_rn(v0.x, v0.y);
    o.h[1] = __floats2half2_rn(v0.z, v0.w);
    o.h[2] = __floats2half2_rn(v1.x, v1.y);
    o.h[3] = __floats2half2_rn(v1.z, v1.w);
    ((uint4*)g_W1h)[i] = o.u;
}

__global__ void convW2_kernel(const float* __restrict__ W2) {
    size_t i = (size_t)blockIdx.x * blockDim.x + threadIdx.x;   // oct over [HID][N2PAD]
    const size_t N = (size_t)HID * N2PAD / 8;
    if (i >= N) return;
    int k = (int)(i / (N2PAD / 8));
    int n = (int)(i % (N2PAD / 8)) * 8;
    float4 v0, v1;
    if (n < ZDIM) {                          // ZDIM%8==0 -> full oct in range
        const float4* s = (const float4*)(W2 + (size_t)k * ZDIM + n);
        v0 = s[0]; v1 = s[1];
    } else {
        v0 = v1 = make_float4(0.f, 0.f, 0.f, 0.f);
    }
    union { __half2 h[4]; uint4 u; } o;
    o.h[0] = __floats2half2_rn(v0.x, v0.y);
    o.h[1] = __floats2half2_rn(v0.z, v0.w);
    o.h[2] = __floats2half2_rn(v1.x, v1.y);
    o.h[3] = __floats2half2_rn(v1.z, v1.w);
    ((uint4*)g_W2h)[i] = o.u;
}

// ---------------- GEMM: 128x128 CTA tile, 4 warps (64x64 each), BK=64, 3-stage cp.async ----------------
// smem stage: A tile at +0 (16KB, 128B rows), B tile at +16384 (16KB, 256B rows), SW swizzle
#define STAGEB 32768
#define SMEM_BYTES (3 * STAGEB)    // 98304 -> 2 CTAs/SM

__device__ __forceinline__ uint32_t s2u(const void* p) {
    return (uint32_t)__cvta_generic_to_shared(p);
}
__device__ __forceinline__ void cp16(uint32_t dst, const void* src) {
    asm volatile("cp.async.cg.shared.global [%0],[%1],16;\n" :: "r"(dst), "l"(src));
}

// MODE 0: g_hpart [split] = zh @ W1h   (split-K 8, NKB=35)
// MODE 1: g_h2part[split] = h  @ W2h   (split-K 2, NKB=32)
template <int MODE>
__global__ __launch_bounds__(128, 2) void gemm_kernel() {
    constexpr int LDA = (MODE == 0) ? ZPAD : HID;
    constexpr int LDB = (MODE == 0) ? HID  : N2PAD;
    constexpr int LDO = (MODE == 0) ? HID  : N2PAD;
    constexpr int NKB = (MODE == 0) ? NKB1 : NKB2;

    extern __shared__ char sm[];
    const uint32_t smb = s2u(sm);
    const int tid = threadIdx.x, lane = tid & 31, warp = tid >> 5;
    const int wm = warp >> 1, wn = warp & 1;      // 2x2 warp grid, 64x64 tiles
    const int n0 = blockIdx.x * 128;
    const int kb0 = blockIdx.y * NKB;

    const __half* A = (MODE == 0) ? g_zh : g_h;
    const __half* B = (MODE == 0) ? g_W1h : g_W2h;
    float* part = ((MODE == 0) ? g_hpart : g_h2part)
                + (size_t)blockIdx.y * NBATCH * LDO;

    // ---- hoisted load setup (128 threads: 8 A-chunks + 8 B-chunks each) ----
    const int am = tid >> 3, ac = tid & 7;      // A: rows am + i*16, chunk ac
    const int bk = tid >> 4, bc = tid & 15;     // B: rows bk + i*8,  chunk bc
    const __half* aptr = A + (size_t)am * LDA + kb0 * 64 + ac * 8;
    const __half* bptr = B + (size_t)(kb0 * 64 + bk) * LDB + n0 + bc * 8;
    const uint32_t aoff = (uint32_t)(am * 128 + ((ac ^ (am & 7)) << 4));          // bytes
    const uint32_t boff = 16384u + (uint32_t)(bk * 256 + ((bc ^ (bk & 7)) << 4)); // bytes

    // ---- hoisted ldmatrix addressing ----
    const int hi = lane >> 4, lo7 = lane & 7, lo15 = lane & 15;
    uint32_t baseA[4], swA[4], preB[4];
#pragma unroll
    for (int f = 0; f < 4; f++) baseA[f] = (uint32_t)((wm * 64 + f * 16 + lo15) * 128);
#pragma unroll
    for (int ks = 0; ks < 4; ks++) swA[ks] = (uint32_t)(((ks * 2 + hi) ^ lo7) << 4);
#pragma unroll
    for (int h = 0; h < 4; h++)
        preB[h] = 16384u + (uint32_t)((((wn * 8 + h * 2 + hi) ^ lo7) << 4) + lo15 * 256);

    float acc[4][8][4];
#pragma unroll
    for (int f = 0; f < 4; f++)
#pragma unroll
        for (int t = 0; t < 8; t++)
#pragma unroll
            for (int i = 0; i < 4; i++) acc[f][t][i] = 0.0f;

    auto load_stage = [&](uint32_t stage) {
#pragma unroll
        for (int i = 0; i < 8; i++) {
            cp16(stage + aoff + i * 2048, aptr + (size_t)i * 16 * LDA);
            cp16(stage + boff + i * 2048, bptr + (size_t)i * 8 * LDB);
        }
        aptr += 64;
        bptr += (size_t)64 * LDB;
    };

    uint32_t s0 = smb, s1 = smb + STAGEB, s2 = smb + 2 * STAGEB;

    // prologue: tiles 0,1 into stages 0,1
    load_stage(s0);
    asm volatile("cp.async.commit_group;\n");
    load_stage(s1);
    asm volatile("cp.async.commit_group;\n");

#pragma unroll 1
    for (int kb = 0; kb < NKB; kb++) {
        asm volatile("cp.async.wait_group %0;\n" :: "n"(1));
        __syncthreads();
        if (kb + 2 < NKB) load_stage(s2);
        asm volatile("cp.async.commit_group;\n");

#pragma unroll
        for (int ks = 0; ks < 4; ks++) {
            uint32_t a[4][4], bf[8][2];
#pragma unroll
            for (int f = 0; f < 4; f++) {
                asm volatile("ldmatrix.sync.aligned.m8n8.x4.shared.b16 {%0,%1,%2,%3},[%4];\n"
                             : "=r"(a[f][0]), "=r"(a[f][1]), "=r"(a[f][2]), "=r"(a[f][3])
                             : "r"(s0 + baseA[f] + swA[ks]));
            }
#pragma unroll
            for (int h = 0; h < 4; h++) {
                uint32_t r0, r1, r2, r3;
                asm volatile("ldmatrix.sync.aligned.m8n8.x4.trans.shared.b16 {%0,%1,%2,%3},[%4];\n"
                             : "=r"(r0), "=r"(r1), "=r"(r2), "=r"(r3)
                             : "r"(s0 + preB[h] + ks * 4096));
                bf[h * 2][0] = r0; bf[h * 2][1] = r1;
                bf[h * 2 + 1][0] = r2; bf[h * 2 + 1][1] = r3;
            }
#pragma unroll
            for (int f = 0; f < 4; f++)
#pragma unroll
                for (int t = 0; t < 8; t++) {
                    asm volatile(
                        "mma.sync.aligned.m16n8k16.row.col.f32.f16.f16.f32 "
                        "{%0,%1,%2,%3},{%4,%5,%6,%7},{%8,%9},{%0,%1,%2,%3};\n"
                        : "+f"(acc[f][t][0]), "+f"(acc[f][t][1]),
                          "+f"(acc[f][t][2]), "+f"(acc[f][t][3])
                        : "r"(a[f][0]), "r"(a[f][1]), "r"(a[f][2]), "r"(a[f][3]),
                          "r"(bf[t][0]), "r"(bf[t][1]));
                }
        }
        // rotate stages
        uint32_t tmp = s0; s0 = s1; s1 = s2; s2 = tmp;
    }

    // epilogue: fp32 partials
#pragma unroll
    for (int f = 0; f < 4; f++) {
        int row = wm * 64 + f * 16 + (lane >> 2);
#pragma unroll
        for (int t = 0; t < 8; t++) {
            int col = n0 + wn * 64 + t * 8 + ((lane & 3) << 1);
            *(float2*)(part + (size_t)row * LDO + col)       = make_float2(acc[f][t][0], acc[f][t][1]);
            *(float2*)(part + (size_t)(row + 8) * LDO + col) = make_float2(acc[f][t][2], acc[f][t][3]);
        }
    }
}

// ---------------- GEMM1 reduce + bias + time-embedding tail + tanh ----------------
__global__ void reduce_tanh_kernel(const float* __restrict__ W1, const float* __restrict__ b1, int t) {
    int idx = blockIdx.x * 256 + threadIdx.x;      // < 128*4096
    int b = idx >> 12, n = idx & 4095;
    float s = b1[n];
#pragma unroll
    for (int p = 0; p < SPLITK1; p++)
        s += g_hpart[(size_t)p * NBATCH * HID + idx];
    const float* e0 = g_emb + (t * NBATCH + b) * 6;
    const float* e1 = e0 + NBATCH * 6;
#pragma unroll
    for (int j = 0; j < 6; j++) s += e0[j] * W1[(size_t)(ZDIM + j) * HID + n];
#pragma unroll
    for (int j = 0; j < 6; j++) s += e1[j] * W1[(size_t)(ZDIM + 6 + j) * HID + n];
    g_h[idx] = __float2half(tanhf(s));
}

// ---------------- GEMM2 reduce: z += p0 + p1 + b2, refresh fp16 z ----------------
__global__ void zupdate_kernel(const float* __restrict__ b2, float* __restrict__ z) {
    int idx = blockIdx.x * 256 + threadIdx.x;
    if (idx >= NBATCH * ZDIM) return;
    int row = idx / ZDIM;
    int col = idx - row * ZDIM;
    size_t po = (size_t)row * N2PAD + col;
    float v = z[idx] + b2[col]
            + g_h2part[po]
            + g_h2part[(size_t)NBATCH * N2PAD + po];
    z[idx] = v;
    g_zh[(size_t)row * ZPAD + col] = __float2half(v);
}

// ---------------- launcher ----------------
extern "C" void kernel_launch(void* const* d_in, const int* in_sizes, int n_in,
                              void* d_out, int out_size) {
    const float* input_freq = (const float*)d_in[0];
    const int*   input_seq  = (const int*)  d_in[1];
    const int*   uid        = (const int*)  d_in[2];
    const float* cur_time   = (const float*)d_in[3];
    const float* tar_time   = (const float*)d_in[4];
    const float* fuse       = (const float*)d_in[5];
    const float* W1         = (const float*)d_in[6];
    const float* b1         = (const float*)d_in[7];
    const float* W2         = (const float*)d_in[8];
    const float* b2         = (const float*)d_in[9];
    const int*   n_poi      = (const int*)  d_in[10];
    float* z = (float*)d_out;

    cudaFuncSetAttribute(gemm_kernel<0>, cudaFuncAttributeMaxDynamicSharedMemorySize, SMEM_BYTES);
    cudaFuncSetAttribute(gemm_kernel<1>, cudaFuncAttributeMaxDynamicSharedMemorySize, SMEM_BYTES);

    emb_kernel<<<1, 128>>>(cur_time, tar_time);
    z0_kernel<<<(NBATCH * ZDIM + 511) / 512, 512>>>(input_freq, input_seq, uid, fuse, n_poi, z);
    zpad_kernel<<<(NBATCH * (ZPAD - ZDIM) / 2 + 255) / 256, 256>>>();

    {   // weight conversion, once per launch (16B loads+stores)
        size_t n1 = (size_t)ZPAD * HID / 8;
        size_t n2 = (size_t)HID * N2PAD / 8;
        convW1_kernel<<<(unsigned)((n1 + 255) / 256), 256>>>(W1);
        convW2_kernel<<<(unsigned)((n2 + 255) / 256), 256>>>(W2);
    }

    for (int t = 0; t < NSTEPS; t++) {
        gemm_kernel<0><<<dim3(HID / 128, SPLITK1), 128, SMEM_BYTES>>>();
        reduce_tanh_kernel<<<NBATCH * HID / 256, 256>>>(W1, b1, t);
        gemm_kernel<1><<<dim3(N2PAD / 128, SPLITK2), 128, SMEM_BYTES>>>();
        zupdate_kernel<<<(NBATCH * ZDIM + 255) / 256, 256>>>(b2, z);
    }
}